// round 14
// baseline (speedup 1.0000x reference)
#include <cuda_runtime.h>
#include <cstdint>

#define BB 4
#define NN 4096
#define CC 80
#define CP1 81
#define KPRE 2000
#define CAPC 2048              // per-class bucket cap
#define NMSCAP 1024            // per-class NMS pool cap
#define SURVCAP 2560           // survivor cap == max taken with 14-bit slack
#define PADF 256               // final-stage selection width (>= 100 + bin slack)
#define NB0 16384              // level-0 bins (key >> 50)
#define W_IMG 1333.0f
#define H_IMG 800.0f
#define SCORE_THR 0.05f
#define MAXPER 100
#define MAX_RATIO 4.135166556742356f   // |ln(16/1000)|
#define CLS_OFFSET 1334.0f             // max(H,W)+1

// ---------------- static scratch (no allocations allowed) ----------------
__device__ unsigned long long g_ckeys[BB][CC][CAPC];    // per-class buckets
__device__ int                g_ccnt[BB][CC];           // reset by k_final
__device__ unsigned long long g_T[BB];                  // top-2000-superset threshold
__device__ unsigned long long g_skey[BB][SURVCAP];      // survivor keys
__device__ float4             g_sbox[BB][SURVCAP];      // survivor boxes
__device__ int                g_scnt[BB];               // reset by k_final
__device__ unsigned int       g_hist0[BB][NB0];         // 14-bit lvl-0 hist (reset by thresh)
__device__ unsigned int       g_hist1[BB][2048];        // survivor lvl-0 hist (reset by k_final)
__device__ int                g_done0[BB];              // score completion (reset by thresh)

// fallback radix levels (exact): bits 14+8*5+10 = 64
__device__ __constant__ int f_shift[7] = {50, 42, 34, 26, 18, 10, 0};
__device__ __constant__ int f_width[7] = {14,  8,  8,  8,  8,  8, 10};

// ---- parallel straddle-bin search over s_hist[NB], NB in [64, 2048] ----
__device__ __forceinline__ void find_straddle(
    unsigned int* s_hist, int NB, int rank, int above0,
    int* s_bin, int* s_binh, int* s_bincg, unsigned int* s_wtot)
{
    int tid = threadIdx.x, lane = tid & 31, w = tid >> 5;
    int nw = NB >> 6;
    unsigned int h0 = 0, h1 = 0, tsum = 0;
    int b0 = tid * 2;
    if (b0 < NB) { h0 = s_hist[b0]; h1 = s_hist[b0 + 1]; tsum = h0 + h1; }
    unsigned int suf = tsum;
    #pragma unroll
    for (int off = 16; off; off >>= 1) {
        unsigned int t = __shfl_down_sync(0xffffffffu, suf, off);
        if (lane + off < 32) suf += t;
    }
    if (lane == 0 && w < nw) s_wtot[w] = suf;
    __syncthreads();
    if (w == 0) {
        unsigned int v = (lane < nw) ? s_wtot[lane] : 0u;
        unsigned int ws = v;
        #pragma unroll
        for (int off = 16; off; off >>= 1) {
            unsigned int t = __shfl_down_sync(0xffffffffu, ws, off);
            if (lane + off < 32) ws += t;
        }
        if (lane < nw) s_wtot[lane] = ws - v;
    }
    __syncthreads();
    if (b0 < NB) {
        unsigned int above_hi = s_wtot[w] + (suf - tsum);
        int a1 = above0 + (int)above_hi;
        int a0 = a1 + (int)h1;
        if (h1 && a1 < rank && a1 + (int)h1 >= rank) { *s_bin = b0 + 1; *s_binh = (int)h1; *s_bincg = a1; }
        if (h0 && a0 < rank && a0 + (int)h0 >= rank) { *s_bin = b0;     *s_binh = (int)h0; *s_bincg = a0; }
    }
    __syncthreads();
}

// ======= kernel 1: softmax+scatter; last block per image runs thresh =========
__global__ void __launch_bounds__(1024)
k_score_thresh(const float* __restrict__ cls) {
    __shared__ unsigned int s_hist[2048];
    __shared__ unsigned int s_wtot[32];
    __shared__ int          s_ccnts[CC];
    __shared__ unsigned long long s_prefix;
    __shared__ int s_above, s_done, s_last;
    __shared__ int s_bin, s_binh, s_bincg;

    int tid = threadIdx.x;
    int row = (blockIdx.x << 10 | tid) >> 3;     // 128 rows per block
    int o = tid & 7;
    int b = row / NN;                            // block-uniform (128 | 4096)

    // ---- score phase ----
    {
        int n = row % NN;
        const float* p = cls + (size_t)row * CP1;
        float v[11];
        #pragma unroll
        for (int k = 0; k < 10; k++) v[k] = p[o + 8 * k];
        v[10] = (o == 0) ? p[80] : -1e30f;

        float m = v[0];
        #pragma unroll
        for (int k = 1; k < 11; k++) m = fmaxf(m, v[k]);
        #pragma unroll
        for (int off = 4; off; off >>= 1) m = fmaxf(m, __shfl_xor_sync(0xffffffffu, m, off));

        float e[11];
        float s = 0.f;
        #pragma unroll
        for (int k = 0; k < 11; k++) { e[k] = expf(v[k] - m); s += e[k]; }
        #pragma unroll
        for (int off = 4; off; off >>= 1) s += __shfl_xor_sync(0xffffffffu, s, off);

        #pragma unroll
        for (int k = 0; k < 10; k++) {
            float sc = e[k] / s;
            if (sc > SCORE_THR) {
                int c = o + 8 * k;
                unsigned int sb = __float_as_uint(sc);
                unsigned int lo = 0xFFFFFFFFu - (unsigned int)(n * CC + c);
                unsigned long long key = ((unsigned long long)sb << 32) | (unsigned long long)lo;
                int cp = atomicAdd(&g_ccnt[b][c], 1);
                if (cp < CAPC) g_ckeys[b][c][cp] = key;
                atomicAdd(&g_hist0[b][(unsigned int)(key >> 50)], 1u);
            }
        }
    }

    // ---- completion: last of 32 blocks for this image runs thresh ----
    __threadfence();
    __syncthreads();
    if (tid == 0) {
        int old = atomicAdd(&g_done0[b], 1);
        s_last = (old == 31) ? 1 : 0;
    }
    __syncthreads();
    if (!s_last) return;

    int lane = tid & 31;
    int wid = tid >> 5;

    if (tid < CC) {
        int cc = g_ccnt[b][tid];
        s_ccnts[tid] = (cc > CAPC) ? CAPC : cc;
    }
    __syncthreads();
    if (tid == 0) {
        g_done0[b] = 0;
        int M = 0;
        for (int c = 0; c < CC; c++) M += s_ccnts[c];
        s_prefix = 0ULL;
        s_above = 0;
        s_binh = 0;
        if (M <= KPRE) { g_T[b] = 1ULL; s_done = 1; } else s_done = 0;
    }
    __syncthreads();

    // ---- level 0: 14-bit straddle from registers (load + reset g_hist0) ----
    {
        unsigned int hv[16];
        int base_bin = tid * 16;
        #pragma unroll
        for (int j = 0; j < 16; j++) {
            hv[j] = g_hist0[b][base_bin + j];
            g_hist0[b][base_bin + j] = 0u;
        }
        if (!s_done) {
            unsigned int tsum = 0;
            #pragma unroll
            for (int j = 0; j < 16; j++) tsum += hv[j];
            unsigned int suf = tsum;                 // warp inclusive suffix
            #pragma unroll
            for (int off = 16; off; off >>= 1) {
                unsigned int t = __shfl_down_sync(0xffffffffu, suf, off);
                if (lane + off < 32) suf += t;
            }
            if (lane == 0) s_wtot[wid] = suf;
            __syncthreads();
            if (wid == 0) {                          // exclusive suffix over warps
                unsigned int v = s_wtot[lane];
                unsigned int ws = v;
                #pragma unroll
                for (int off = 16; off; off >>= 1) {
                    unsigned int t = __shfl_down_sync(0xffffffffu, ws, off);
                    if (lane + off < 32) ws += t;
                }
                s_wtot[lane] = ws - v;
            }
            __syncthreads();
            unsigned int cg = s_wtot[wid] + (suf - tsum);   // keys above my chunk
            #pragma unroll
            for (int j = 15; j >= 0; j--) {
                unsigned int h = hv[j];
                int a = (int)cg;
                if (h && a < KPRE && a + (int)h >= KPRE) {
                    s_bin = base_bin + j; s_binh = (int)h; s_bincg = a;
                }
                cg += h;
            }
            __syncthreads();
            if (tid == 0) {
                int a = s_bincg, h = s_binh;
                unsigned long long binv = (unsigned long long)s_bin << 50;
                if (h == 0) { g_T[b] = s_prefix; s_done = 1; }     // safety
                else if (a + h <= SURVCAP) {                       // slack accept
                    g_T[b] = s_prefix | binv; s_done = 1;
                } else { s_prefix = s_prefix | binv; s_above = a; }
            }
            __syncthreads();
        }
    }

    // ---- fallback: exact descent, global scans (rare) ----
    for (int level = 1; level < 7 && !s_done; level++) {
        int shift = f_shift[level];
        int width = f_width[level];
        int NB = 1 << width;
        unsigned long long pmask = (~0ULL) << (shift + width);
        for (int i = tid; i < NB; i += 1024) s_hist[i] = 0;
        if (tid == 0) s_binh = 0;
        __syncthreads();
        unsigned long long pref = s_prefix;
        for (int c = wid; c < CC; c += 32) {
            int cnt = s_ccnts[c];
            for (int i = lane; i < cnt; i += 32) {
                unsigned long long k = g_ckeys[b][c][i];
                if ((k & pmask) == pref)
                    atomicAdd(&s_hist[(unsigned int)(k >> shift) & (NB - 1)], 1u);
            }
        }
        __syncthreads();
        find_straddle(s_hist, NB, KPRE, s_above, &s_bin, &s_binh, &s_bincg, s_wtot);
        if (tid == 0) {
            int a = s_bincg, h = s_binh;
            unsigned long long binv = (unsigned long long)s_bin << shift;
            if (h == 0) { g_T[b] = s_prefix; s_done = 1; }          // safety
            else if (a + h <= SURVCAP || level == 6) {              // exact at lvl 6
                g_T[b] = s_prefix | binv; s_done = 1;
            } else { s_prefix = s_prefix | binv; s_above = a; }
        }
        __syncthreads();
    }
}

// ---------------- 2: per-class NMS, one 128-thread block per (class, image) --
__global__ void k_nms(const float* __restrict__ reg, const float* __restrict__ rois) {
    __shared__ unsigned long long s_k[NMSCAP];
    __shared__ float4             s_bx[NMSCAP];
    __shared__ unsigned char      s_sup[NMSCAP];
    __shared__ short              s_keep[NMSCAP];
    __shared__ int s_cnt, s_n, s_nk, s_base;

    int c = blockIdx.x;
    int b = blockIdx.y;
    int tid = threadIdx.x;
    int lane = tid & 31;

    if (tid == 0) {
        int cc = g_ccnt[b][c]; if (cc > CAPC) cc = CAPC;
        s_cnt = cc;
        s_n = 0; s_nk = 0; s_base = 0;
    }
    __syncthreads();
    int cnt = s_cnt;
    unsigned long long T = g_T[b];

    // filter >= T, warp-aggregated append (uniform trips)
    int iters = (cnt + 127) >> 7;
    for (int it = 0; it < iters; it++) {
        int i = (it << 7) + tid;
        unsigned long long k = (i < cnt) ? g_ckeys[b][c][i] : 0ULL;
        bool f = (i < cnt) && (k >= T);
        unsigned bal = __ballot_sync(0xffffffffu, f);
        int wc = __popc(bal);
        int base = 0;
        if (lane == 0 && wc) base = atomicAdd(&s_n, wc);
        base = __shfl_sync(0xffffffffu, base, 0);
        if (f) {
            int pos = base + __popc(bal & ((1u << lane) - 1));
            if (pos < NMSCAP) s_k[pos] = k;
        }
    }
    __syncthreads();
    int n = s_n; if (n > NMSCAP) n = NMSCAP;

    // pad to pow2; warp-0 bitonic sort (descending), __syncwarp only
    int p = 2; while (p < n) p <<= 1;
    for (int i = n + tid; i < p; i += blockDim.x) s_k[i] = 0ULL;
    __syncthreads();
    if (tid < 32) {
        for (int k2 = 2; k2 <= p; k2 <<= 1) {
            for (int j = k2 >> 1; j > 0; j >>= 1) {
                for (int i = lane; i < p; i += 32) {
                    int ixj = i ^ j;
                    if (ixj > i) {
                        unsigned long long a = s_k[i];
                        unsigned long long d = s_k[ixj];
                        bool desc = ((i & k2) == 0);
                        if (desc ? (a < d) : (a > d)) { s_k[i] = d; s_k[ixj] = a; }
                    }
                }
                __syncwarp();
            }
        }
    }
    __syncthreads();

    // decode + clip
    for (int i = tid; i < n; i += blockDim.x) {
        unsigned long long key = s_k[i];
        unsigned int idx = 0xFFFFFFFFu - (unsigned int)(key & 0xFFFFFFFFu);
        int nn = idx / CC;
        const float* r = rois + ((size_t)b * NN + nn) * 4;
        float x1 = r[0], y1 = r[1], x2 = r[2], y2 = r[3];
        float px = (x1 + x2) * 0.5f;
        float py = (y1 + y2) * 0.5f;
        float pw = x2 - x1;
        float ph = y2 - y1;
        const float* d = reg + ((size_t)b * NN + nn) * (4 * CC) + 4 * c;
        float dx = d[0] * 0.1f;
        float dy = d[1] * 0.1f;
        float dw = fminf(d[2] * 0.2f, MAX_RATIO);
        float dh = fminf(d[3] * 0.2f, MAX_RATIO);
        float gx = px + pw * dx;
        float gy = py + ph * dy;
        float gw = pw * expf(dw);
        float gh = ph * expf(dh);
        float bx1 = gx - gw * 0.5f, by1 = gy - gh * 0.5f;
        float bx2 = gx + gw * 0.5f, by2 = gy + gh * 0.5f;
        bx1 = fminf(fmaxf(bx1, 0.f), W_IMG);
        bx2 = fminf(fmaxf(bx2, 0.f), W_IMG);
        by1 = fminf(fmaxf(by1, 0.f), H_IMG);
        by2 = fminf(fmaxf(by2, 0.f), H_IMG);
        s_bx[i] = make_float4(bx1, by1, bx2, by2);
        s_sup[i] = 0;
    }
    __syncthreads();

    // greedy NMS (warp 0); IoU on OFFSET boxes = exact reference arithmetic
    if (tid < 32) {
        float off = (float)c * CLS_OFFSET;
        for (int ii = 0; ii < n; ii++) {
            if (!s_sup[ii]) {
                float4 bi = s_bx[ii];
                bi.x += off; bi.y += off; bi.z += off; bi.w += off;
                float ai = (bi.z - bi.x) * (bi.w - bi.y);
                for (int jj = ii + 1 + lane; jj < n; jj += 32) {
                    float4 bj = s_bx[jj];
                    bj.x += off; bj.y += off; bj.z += off; bj.w += off;
                    float xx1 = fmaxf(bi.x, bj.x);
                    float yy1 = fmaxf(bi.y, bj.y);
                    float xx2 = fminf(bi.z, bj.z);
                    float yy2 = fminf(bi.w, bj.w);
                    float iw = fmaxf(xx2 - xx1, 0.f);
                    float ih = fmaxf(yy2 - yy1, 0.f);
                    float inter = iw * ih;
                    float aj = (bj.z - bj.x) * (bj.w - bj.y);
                    float uni = fmaxf(ai + aj - inter, 1e-6f);
                    if (inter / uni > 0.5f) s_sup[jj] = 1;
                }
            }
            __syncwarp();
        }
        if (lane == 0) {
            int mkeep = 0;
            for (int i = 0; i < n; i++)
                if (!s_sup[i]) s_keep[mkeep++] = (short)i;
            s_nk = mkeep;
            if (mkeep) s_base = atomicAdd(&g_scnt[b], mkeep);
        }
    }
    __syncthreads();
    int nk = s_nk, sb = s_base;
    for (int i = tid; i < nk; i += blockDim.x) {
        if (sb + i < SURVCAP) {
            int src = s_keep[i];
            unsigned long long k = s_k[src];
            g_skey[b][sb + i] = k;
            g_sbox[b][sb + i] = s_bx[src];
            atomicAdd(&g_hist1[b][(unsigned int)(k >> 53) & 2047u], 1u);
        }
    }
}

// ---------------- 3: top-100 of survivors by RANK, output, resets ------------
__global__ void __launch_bounds__(1024)
k_final(float* __restrict__ out) {
    __shared__ unsigned int       s_hist[2048];
    __shared__ unsigned int       s_wtot[32];
    __shared__ unsigned long long s_prefix;
    __shared__ unsigned long long s_T;
    __shared__ int s_above, s_done, s_S, s_cnt;
    __shared__ int s_bin, s_binh, s_bincg;
    __shared__ unsigned long long s_k2[PADF];
    __shared__ short              s_slot[PADF];

    int b = blockIdx.x;
    int tid = threadIdx.x;
    int lane = tid & 31;
    const unsigned long long* keys = g_skey[b];

    if (tid == 0) {
        int S = g_scnt[b]; if (S > SURVCAP) S = SURVCAP;
        s_S = S;
        s_prefix = 0ULL;
        s_above = 0;
        s_done = (S <= PADF) ? 1 : 0;
        s_T = 1ULL;
        s_cnt = 0;
    }
    __syncthreads();
    int S = s_S;

    // rank-100 radix with slack; level 0 (11-bit, shift 53) precomputed by k_nms
    for (int level = 0; level < 6 && !s_done; level++) {
        int shift, width;
        if (level == 0) { shift = 53; width = 11; }
        else { shift = 53 - 11 * level; if (shift < 0) shift = 0; width = 11; }
        // levels: 53,42,31,20,9,0 — widths 11 except last effectively 9
        if (level == 5) { shift = 0; width = 9; }
        int NB = 1 << width;
        if (level == 0) {
            for (int i = tid; i < 2048; i += 1024) s_hist[i] = g_hist1[b][i];
        } else {
            unsigned long long pmask = (~0ULL) << (shift + width);
            for (int i = tid; i < NB; i += 1024) s_hist[i] = 0;
            __syncthreads();
            unsigned long long pref = s_prefix;
            for (int i = tid; i < S; i += 1024) {
                unsigned long long k = keys[i];
                if ((k & pmask) == pref)
                    atomicAdd(&s_hist[(unsigned int)(k >> shift) & (NB - 1)], 1u);
            }
        }
        if (tid == 0) s_binh = 0;
        __syncthreads();
        find_straddle(s_hist, NB, MAXPER, s_above, &s_bin, &s_binh, &s_bincg, s_wtot);
        if (tid == 0) {
            int a = s_bincg, h = s_binh;
            unsigned long long binv = (unsigned long long)s_bin << shift;
            if (h == 0) { s_done = 1; }
            else if (a + h <= PADF) { s_T = s_prefix | binv; s_done = 1; }
            else { s_prefix = s_prefix | binv; s_above = a; }
        }
        __syncthreads();
    }
    unsigned long long T2 = s_T;

    // compact (key, slot) pairs >= T2 directly from global (uniform trips)
    {
        int iters = (S + 1023) >> 10;
        for (int it = 0; it < iters; it++) {
            int i = (it << 10) + tid;
            unsigned long long k = (i < S) ? keys[i] : 0ULL;
            bool f = (i < S) && (k >= T2);
            unsigned bal = __ballot_sync(0xffffffffu, f);
            int wc = __popc(bal);
            int base = 0;
            if (lane == 0 && wc) base = atomicAdd(&s_cnt, wc);
            base = __shfl_sync(0xffffffffu, base, 0);
            if (f) {
                int pos = base + __popc(bal & ((1u << lane) - 1));
                if (pos < PADF) { s_k2[pos] = k; s_slot[pos] = (short)i; }
            }
        }
    }
    __syncthreads();
    int cf = s_cnt; if (cf > PADF) cf = PADF;

    // prefill output with empty slots
    if (tid < MAXPER) {
        float* po = out + ((size_t)b * MAXPER + tid) * 4;
        po[0] = 0.f; po[1] = 0.f; po[2] = 0.f; po[3] = 0.f;
        out[BB * MAXPER * 4 + b * MAXPER + tid] = 0.f;
        out[BB * MAXPER * 4 + BB * MAXPER + b * MAXPER + tid] = -1.f;
    }
    __syncthreads();

    // rank selection: keys unique -> exact permutation; rank < 100 writes slot
    if (tid < cf) {
        unsigned long long mykey = s_k2[tid];
        int r = 0;
        for (int j = 0; j < cf; j++) r += (s_k2[j] > mykey) ? 1 : 0;
        if (r < MAXPER) {
            float4 bb = g_sbox[b][s_slot[tid]];
            float sc = __uint_as_float((unsigned int)(mykey >> 32));
            unsigned int idx = 0xFFFFFFFFu - (unsigned int)(mykey & 0xFFFFFFFFu);
            float lb = (float)(idx % CC);
            float* po = out + ((size_t)b * MAXPER + r) * 4;
            po[0] = bb.x; po[1] = bb.y; po[2] = bb.z; po[3] = bb.w;
            out[BB * MAXPER * 4 + b * MAXPER + r] = sc;
            out[BB * MAXPER * 4 + BB * MAXPER + b * MAXPER + r] = lb;
        }
    }

    // global resets for next graph replay
    for (int i = tid; i < 2048; i += 1024) g_hist1[b][i] = 0u;
    if (tid < CC) g_ccnt[b][tid] = 0;
    if (tid == 0) g_scnt[b] = 0;
}

extern "C" void kernel_launch(void* const* d_in, const int* in_sizes, int n_in,
                              void* d_out, int out_size) {
    const float* cls  = (const float*)d_in[0];   // [B,N,81]
    const float* reg  = (const float*)d_in[1];   // [B,N,320]
    const float* rois = (const float*)d_in[2];   // [B,N,4]
    float* out = (float*)d_out;

    k_score_thresh<<<BB * NN * 8 / 1024, 1024>>>(cls);
    k_nms<<<dim3(CC, BB), 128>>>(reg, rois);
    k_final<<<BB, 1024>>>(out);
}

// round 15
// speedup vs baseline: 1.0585x; 1.0585x over previous
#include <cuda_runtime.h>
#include <cstdint>

#define BB 4
#define NN 4096
#define CC 80
#define CP1 81
#define KPRE 2000
#define CAPC 2048              // per-class bucket cap
#define NMSCAP 1024            // per-class NMS pool cap
#define TSTAGE 2048            // thresh staging cap
#define PADF 256               // final-stage selection width (>= 100 + bin slack)
#define W_IMG 1333.0f
#define H_IMG 800.0f
#define SCORE_THR 0.05f
#define MAXPER 100
#define MAX_RATIO 4.135166556742356f   // |ln(16/1000)|
#define CLS_OFFSET 1334.0f             // max(H,W)+1

// ---------------- static scratch (no allocations allowed) ----------------
__device__ unsigned long long g_ckeys[BB][CC][CAPC];    // per-class buckets
__device__ int                g_ccnt[BB][CC];           // reset by k_final
__device__ unsigned long long g_T[BB];                  // exact rank-2000 threshold
__device__ unsigned long long g_skey[BB][KPRE];         // survivor keys
__device__ float4             g_sbox[BB][KPRE];         // survivor boxes
__device__ int                g_scnt[BB];               // reset by k_final
__device__ unsigned int       g_hist0[BB][2048];        // candidate lvl-0 hist (reset by thresh)
__device__ unsigned int       g_hist1[BB][2048];        // survivor lvl-0 hist (reset by k_final)
__device__ int                g_done0[BB];              // score completion (reset by thresh)

// radix level config: 11-bit fields, last level 9 bits (covers all 64 bits)
__device__ __constant__ int c_shift[6] = {53, 42, 31, 20, 9, 0};
__device__ __constant__ int c_width[6] = {11, 11, 11, 11, 11, 9};

// ---- parallel straddle-bin search over s_hist[NB] (blockDim.x == 1024) ----
__device__ __forceinline__ void find_straddle(
    unsigned int* s_hist, int NB, int rank, int above0,
    int* s_bin, int* s_binh, int* s_bincg, unsigned int* s_wtot)
{
    int tid = threadIdx.x, lane = tid & 31, w = tid >> 5;
    int nw = NB >> 6;
    unsigned int h0 = 0, h1 = 0, tsum = 0;
    int b0 = tid * 2;
    if (b0 < NB) { h0 = s_hist[b0]; h1 = s_hist[b0 + 1]; tsum = h0 + h1; }
    unsigned int suf = tsum;
    #pragma unroll
    for (int off = 16; off; off >>= 1) {
        unsigned int t = __shfl_down_sync(0xffffffffu, suf, off);
        if (lane + off < 32) suf += t;
    }
    if (lane == 0 && w < nw) s_wtot[w] = suf;
    __syncthreads();
    if (w == 0) {
        unsigned int v = (lane < nw) ? s_wtot[lane] : 0u;
        unsigned int ws = v;
        #pragma unroll
        for (int off = 16; off; off >>= 1) {
            unsigned int t = __shfl_down_sync(0xffffffffu, ws, off);
            if (lane + off < 32) ws += t;
        }
        if (lane < nw) s_wtot[lane] = ws - v;
    }
    __syncthreads();
    if (b0 < NB) {
        unsigned int above_hi = s_wtot[w] + (suf - tsum);
        int a1 = above0 + (int)above_hi;
        int a0 = a1 + (int)h1;
        if (h1 && a1 < rank && a1 + (int)h1 >= rank) { *s_bin = b0 + 1; *s_binh = (int)h1; *s_bincg = a1; }
        if (h0 && a0 < rank && a0 + (int)h0 >= rank) { *s_bin = b0;     *s_binh = (int)h0; *s_bincg = a0; }
    }
    __syncthreads();
}

// ======= kernel 1: softmax+scatter; last block per image runs thresh =========
__global__ void __launch_bounds__(1024)
k_score_thresh(const float* __restrict__ cls) {
    __shared__ unsigned int       s_hist[2048];
    __shared__ unsigned long long s_stage[TSTAGE];
    __shared__ unsigned int       s_wtot[32];
    __shared__ int                s_ccnts[CC];
    __shared__ unsigned long long s_prefix;
    __shared__ int s_above, s_done, s_scn, s_tmpc, s_hd, s_last;
    __shared__ int s_bin, s_binh, s_bincg;

    int tid = threadIdx.x;
    int row = (blockIdx.x << 10 | tid) >> 3;     // 128 rows per block
    int o = tid & 7;
    int b = row / NN;                            // block-uniform (128 | 4096)

    // ---- score phase ----
    {
        int n = row % NN;
        const float* p = cls + (size_t)row * CP1;
        float v[11];
        #pragma unroll
        for (int k = 0; k < 10; k++) v[k] = p[o + 8 * k];
        v[10] = (o == 0) ? p[80] : -1e30f;

        float m = v[0];
        #pragma unroll
        for (int k = 1; k < 11; k++) m = fmaxf(m, v[k]);
        #pragma unroll
        for (int off = 4; off; off >>= 1) m = fmaxf(m, __shfl_xor_sync(0xffffffffu, m, off));

        float e[11];
        float s = 0.f;
        #pragma unroll
        for (int k = 0; k < 11; k++) { e[k] = expf(v[k] - m); s += e[k]; }
        #pragma unroll
        for (int off = 4; off; off >>= 1) s += __shfl_xor_sync(0xffffffffu, s, off);

        #pragma unroll
        for (int k = 0; k < 10; k++) {
            float sc = e[k] / s;
            if (sc > SCORE_THR) {
                int c = o + 8 * k;
                unsigned int sb = __float_as_uint(sc);
                unsigned int lo = 0xFFFFFFFFu - (unsigned int)(n * CC + c);
                unsigned long long key = ((unsigned long long)sb << 32) | (unsigned long long)lo;
                int cp = atomicAdd(&g_ccnt[b][c], 1);
                if (cp < CAPC) g_ckeys[b][c][cp] = key;
                atomicAdd(&g_hist0[b][(unsigned int)(key >> 53)], 1u);
            }
        }
    }

    // ---- completion: last of 32 blocks for this image runs thresh ----
    __threadfence();
    __syncthreads();
    if (tid == 0) {
        int old = atomicAdd(&g_done0[b], 1);
        s_last = (old == 31) ? 1 : 0;
    }
    __syncthreads();
    if (!s_last) return;

    int lane = tid & 31;
    int wid = tid >> 5;

    if (tid < CC) {
        int cc = g_ccnt[b][tid];
        s_ccnts[tid] = (cc > CAPC) ? CAPC : cc;
    }
    __syncthreads();
    if (tid == 0) {
        g_done0[b] = 0;                 // reset for next replay
        int M = 0;
        for (int c = 0; c < CC; c++) M += s_ccnts[c];
        s_prefix = 0ULL;
        s_above = 0;
        s_scn = -1;
        s_hd = TSTAGE + 1;
        if (M <= KPRE) { g_T[b] = 1ULL; s_done = 1; } else s_done = 0;
    }
    __syncthreads();

    for (int level = 0; level < 6 && !s_done; level++) {
        int shift = c_shift[level];
        int width = c_width[level];
        int NB = 1 << width;
        if (level == 0) {
            for (int i = tid; i < 2048; i += 1024) {
                s_hist[i] = g_hist0[b][i];
                g_hist0[b][i] = 0u;
            }
        } else {
            unsigned long long pmask = (~0ULL) << (shift + width);
            for (int i = tid; i < 2048; i += 1024) s_hist[i] = 0;
            if (tid == 0) s_tmpc = 0;
            __syncthreads();
            unsigned long long pref = s_prefix;
            if (s_scn < 0) {
                // FUSED: histogram scan + one-time staging in a single pass
                int do_stage = (s_hd <= TSTAGE) ? 1 : 0;   // uniform (shared, post-barrier)
                for (int c = wid; c < CC; c += 32) {
                    int cnt = s_ccnts[c];
                    int iters = (cnt + 31) >> 5;           // warp-uniform trips
                    for (int it = 0; it < iters; it++) {
                        int i = (it << 5) + lane;
                        unsigned long long k = (i < cnt) ? g_ckeys[b][c][i] : 0ULL;
                        bool f = (i < cnt) && ((k & pmask) == pref);
                        if (f) atomicAdd(&s_hist[(unsigned int)(k >> shift) & (NB - 1)], 1u);
                        if (do_stage) {
                            unsigned bal = __ballot_sync(0xffffffffu, f);
                            int wc = __popc(bal);
                            int base = 0;
                            if (lane == 0 && wc) base = atomicAdd(&s_tmpc, wc);
                            base = __shfl_sync(0xffffffffu, base, 0);
                            if (f) s_stage[base + __popc(bal & ((1u << lane) - 1))] = k;
                        }
                    }
                }
                __syncthreads();
                if (tid == 0 && do_stage) s_scn = s_tmpc;   // used from next level on
            } else {
                int sn = s_scn;
                for (int i = tid; i < sn; i += 1024) {
                    unsigned long long k = s_stage[i];
                    if ((k & pmask) == pref)
                        atomicAdd(&s_hist[(unsigned int)(k >> shift) & (NB - 1)], 1u);
                }
            }
        }
        if (tid == 0) s_binh = 0;
        __syncthreads();
        find_straddle(s_hist, NB, KPRE, s_above, &s_bin, &s_binh, &s_bincg, s_wtot);
        if (tid == 0) {
            int a = s_bincg, h = s_binh;
            unsigned long long binv = (unsigned long long)s_bin << shift;
            if (h == 0) { g_T[b] = s_prefix; s_done = 1; }    // safety
            else if (a + h == KPRE) { g_T[b] = s_prefix | binv; s_done = 1; }
            else { s_prefix = s_prefix | binv; s_above = a; s_hd = h; }
        }
        __syncthreads();
    }
    if (s_done) {
        for (int i = tid; i < 2048; i += 1024) g_hist0[b][i] = 0u;  // idempotent
    }
}

// ---------------- 2: per-class NMS, one 128-thread block per (class, image) --
__global__ void k_nms(const float* __restrict__ reg, const float* __restrict__ rois) {
    __shared__ unsigned long long s_k[NMSCAP];
    __shared__ float4             s_bx[NMSCAP];
    __shared__ unsigned char      s_sup[NMSCAP];
    __shared__ short              s_keep[NMSCAP];
    __shared__ int s_cnt, s_n, s_nk, s_base;

    int c = blockIdx.x;
    int b = blockIdx.y;
    int tid = threadIdx.x;
    int lane = tid & 31;

    if (tid == 0) {
        int cc = g_ccnt[b][c]; if (cc > CAPC) cc = CAPC;
        s_cnt = cc;
        s_n = 0; s_nk = 0; s_base = 0;
    }
    __syncthreads();
    int cnt = s_cnt;
    unsigned long long T = g_T[b];

    // filter >= T, warp-aggregated append (uniform trips)
    int iters = (cnt + 127) >> 7;
    for (int it = 0; it < iters; it++) {
        int i = (it << 7) + tid;
        unsigned long long k = (i < cnt) ? g_ckeys[b][c][i] : 0ULL;
        bool f = (i < cnt) && (k >= T);
        unsigned bal = __ballot_sync(0xffffffffu, f);
        int wc = __popc(bal);
        int base = 0;
        if (lane == 0 && wc) base = atomicAdd(&s_n, wc);
        base = __shfl_sync(0xffffffffu, base, 0);
        if (f) {
            int pos = base + __popc(bal & ((1u << lane) - 1));
            if (pos < NMSCAP) s_k[pos] = k;
        }
    }
    __syncthreads();
    int n = s_n; if (n > NMSCAP) n = NMSCAP;

    // pad to pow2; warp-0 bitonic sort (descending), __syncwarp only
    int p = 2; while (p < n) p <<= 1;
    for (int i = n + tid; i < p; i += blockDim.x) s_k[i] = 0ULL;
    __syncthreads();
    if (tid < 32) {
        for (int k2 = 2; k2 <= p; k2 <<= 1) {
            for (int j = k2 >> 1; j > 0; j >>= 1) {
                for (int i = lane; i < p; i += 32) {
                    int ixj = i ^ j;
                    if (ixj > i) {
                        unsigned long long a = s_k[i];
                        unsigned long long d = s_k[ixj];
                        bool desc = ((i & k2) == 0);
                        if (desc ? (a < d) : (a > d)) { s_k[i] = d; s_k[ixj] = a; }
                    }
                }
                __syncwarp();
            }
        }
    }
    __syncthreads();

    // decode + clip
    for (int i = tid; i < n; i += blockDim.x) {
        unsigned long long key = s_k[i];
        unsigned int idx = 0xFFFFFFFFu - (unsigned int)(key & 0xFFFFFFFFu);
        int nn = idx / CC;
        const float* r = rois + ((size_t)b * NN + nn) * 4;
        float x1 = r[0], y1 = r[1], x2 = r[2], y2 = r[3];
        float px = (x1 + x2) * 0.5f;
        float py = (y1 + y2) * 0.5f;
        float pw = x2 - x1;
        float ph = y2 - y1;
        const float* d = reg + ((size_t)b * NN + nn) * (4 * CC) + 4 * c;
        float dx = d[0] * 0.1f;
        float dy = d[1] * 0.1f;
        float dw = fminf(d[2] * 0.2f, MAX_RATIO);
        float dh = fminf(d[3] * 0.2f, MAX_RATIO);
        float gx = px + pw * dx;
        float gy = py + ph * dy;
        float gw = pw * expf(dw);
        float gh = ph * expf(dh);
        float bx1 = gx - gw * 0.5f, by1 = gy - gh * 0.5f;
        float bx2 = gx + gw * 0.5f, by2 = gy + gh * 0.5f;
        bx1 = fminf(fmaxf(bx1, 0.f), W_IMG);
        bx2 = fminf(fmaxf(bx2, 0.f), W_IMG);
        by1 = fminf(fmaxf(by1, 0.f), H_IMG);
        by2 = fminf(fmaxf(by2, 0.f), H_IMG);
        s_bx[i] = make_float4(bx1, by1, bx2, by2);
        s_sup[i] = 0;
    }
    __syncthreads();

    // greedy NMS (warp 0); IoU on OFFSET boxes = exact reference arithmetic
    if (tid < 32) {
        float off = (float)c * CLS_OFFSET;
        for (int ii = 0; ii < n; ii++) {
            if (!s_sup[ii]) {
                float4 bi = s_bx[ii];
                bi.x += off; bi.y += off; bi.z += off; bi.w += off;
                float ai = (bi.z - bi.x) * (bi.w - bi.y);
                for (int jj = ii + 1 + lane; jj < n; jj += 32) {
                    float4 bj = s_bx[jj];
                    bj.x += off; bj.y += off; bj.z += off; bj.w += off;
                    float xx1 = fmaxf(bi.x, bj.x);
                    float yy1 = fmaxf(bi.y, bj.y);
                    float xx2 = fminf(bi.z, bj.z);
                    float yy2 = fminf(bi.w, bj.w);
                    float iw = fmaxf(xx2 - xx1, 0.f);
                    float ih = fmaxf(yy2 - yy1, 0.f);
                    float inter = iw * ih;
                    float aj = (bj.z - bj.x) * (bj.w - bj.y);
                    float uni = fmaxf(ai + aj - inter, 1e-6f);
                    if (inter / uni > 0.5f) s_sup[jj] = 1;
                }
            }
            __syncwarp();
        }
        if (lane == 0) {
            int mkeep = 0;
            for (int i = 0; i < n; i++)
                if (!s_sup[i]) s_keep[mkeep++] = (short)i;
            s_nk = mkeep;
            if (mkeep) s_base = atomicAdd(&g_scnt[b], mkeep);
        }
    }
    __syncthreads();
    int nk = s_nk, sb = s_base;
    for (int i = tid; i < nk; i += blockDim.x) {
        int src = s_keep[i];
        unsigned long long k = s_k[src];
        g_skey[b][sb + i] = k;
        g_sbox[b][sb + i] = s_bx[src];
        atomicAdd(&g_hist1[b][(unsigned int)(k >> 53) & 2047u], 1u);
    }
}

// ---------------- 3: top-100 of survivors by RANK, output, resets ------------
__global__ void __launch_bounds__(1024)
k_final(float* __restrict__ out) {
    __shared__ unsigned int       s_hist[2048];
    __shared__ unsigned int       s_wtot[32];
    __shared__ unsigned long long s_prefix;
    __shared__ unsigned long long s_T;
    __shared__ int s_above, s_done, s_S, s_cnt;
    __shared__ int s_bin, s_binh, s_bincg;
    __shared__ unsigned long long s_k2[PADF];
    __shared__ short              s_slot[PADF];

    int b = blockIdx.x;
    int tid = threadIdx.x;
    int lane = tid & 31;
    const unsigned long long* keys = g_skey[b];

    if (tid == 0) {
        int S = g_scnt[b]; if (S > KPRE) S = KPRE;
        s_S = S;
        s_prefix = 0ULL;
        s_above = 0;
        s_done = (S <= PADF) ? 1 : 0;
        s_T = 1ULL;
        s_cnt = 0;
    }
    __syncthreads();
    int S = s_S;

    // rank-100 radix with slack; level 0 hist precomputed by k_nms
    for (int level = 0; level < 6 && !s_done; level++) {
        int shift = c_shift[level];
        int width = c_width[level];
        int NB = 1 << width;
        if (level == 0) {
            for (int i = tid; i < 2048; i += 1024) s_hist[i] = g_hist1[b][i];
        } else {
            unsigned long long pmask = (~0ULL) << (shift + width);
            for (int i = tid; i < 2048; i += 1024) s_hist[i] = 0;
            __syncthreads();
            unsigned long long pref = s_prefix;
            for (int i = tid; i < S; i += 1024) {
                unsigned long long k = keys[i];
                if ((k & pmask) == pref)
                    atomicAdd(&s_hist[(unsigned int)(k >> shift) & (NB - 1)], 1u);
            }
        }
        if (tid == 0) s_binh = 0;
        __syncthreads();
        find_straddle(s_hist, NB, MAXPER, s_above, &s_bin, &s_binh, &s_bincg, s_wtot);
        if (tid == 0) {
            int a = s_bincg, h = s_binh;
            unsigned long long binv = (unsigned long long)s_bin << shift;
            if (h == 0) { s_done = 1; }
            else if (a + h <= PADF) { s_T = s_prefix | binv; s_done = 1; }
            else { s_prefix = s_prefix | binv; s_above = a; }
        }
        __syncthreads();
    }
    unsigned long long T2 = s_T;

    // compact (key, slot) pairs >= T2 directly from global (uniform trips)
    {
        int iters = (S + 1023) >> 10;
        for (int it = 0; it < iters; it++) {
            int i = (it << 10) + tid;
            unsigned long long k = (i < S) ? keys[i] : 0ULL;
            bool f = (i < S) && (k >= T2);
            unsigned bal = __ballot_sync(0xffffffffu, f);
            int wc = __popc(bal);
            int base = 0;
            if (lane == 0 && wc) base = atomicAdd(&s_cnt, wc);
            base = __shfl_sync(0xffffffffu, base, 0);
            if (f) {
                int pos = base + __popc(bal & ((1u << lane) - 1));
                if (pos < PADF) { s_k2[pos] = k; s_slot[pos] = (short)i; }
            }
        }
    }
    __syncthreads();
    int cf = s_cnt; if (cf > PADF) cf = PADF;

    // prefill output with empty slots
    if (tid < MAXPER) {
        float* po = out + ((size_t)b * MAXPER + tid) * 4;
        po[0] = 0.f; po[1] = 0.f; po[2] = 0.f; po[3] = 0.f;
        out[BB * MAXPER * 4 + b * MAXPER + tid] = 0.f;
        out[BB * MAXPER * 4 + BB * MAXPER + b * MAXPER + tid] = -1.f;
    }
    __syncthreads();

    // rank selection: keys unique -> exact permutation; rank < 100 writes slot
    if (tid < cf) {
        unsigned long long mykey = s_k2[tid];
        int r = 0;
        for (int j = 0; j < cf; j++) r += (s_k2[j] > mykey) ? 1 : 0;
        if (r < MAXPER) {
            float4 bb = g_sbox[b][s_slot[tid]];
            float sc = __uint_as_float((unsigned int)(mykey >> 32));
            unsigned int idx = 0xFFFFFFFFu - (unsigned int)(mykey & 0xFFFFFFFFu);
            float lb = (float)(idx % CC);
            float* po = out + ((size_t)b * MAXPER + r) * 4;
            po[0] = bb.x; po[1] = bb.y; po[2] = bb.z; po[3] = bb.w;
            out[BB * MAXPER * 4 + b * MAXPER + r] = sc;
            out[BB * MAXPER * 4 + BB * MAXPER + b * MAXPER + r] = lb;
        }
    }

    // global resets for next graph replay
    for (int i = tid; i < 2048; i += 1024) g_hist1[b][i] = 0u;
    if (tid < CC) g_ccnt[b][tid] = 0;
    if (tid == 0) g_scnt[b] = 0;
}

extern "C" void kernel_launch(void* const* d_in, const int* in_sizes, int n_in,
                              void* d_out, int out_size) {
    const float* cls  = (const float*)d_in[0];   // [B,N,81]
    const float* reg  = (const float*)d_in[1];   // [B,N,320]
    const float* rois = (const float*)d_in[2];   // [B,N,4]
    float* out = (float*)d_out;

    k_score_thresh<<<BB * NN * 8 / 1024, 1024>>>(cls);
    k_nms<<<dim3(CC, BB), 128>>>(reg, rois);
    k_final<<<BB, 1024>>>(out);
}

// round 17
// speedup vs baseline: 1.1195x; 1.0577x over previous
#include <cuda_runtime.h>
#include <cstdint>

#define BB 4
#define NN 4096
#define CC 80
#define CP1 81
#define KPRE 2000
#define CAPC 2048              // per-class bucket cap
#define NMSCAP 1024            // per-class NMS pool cap
#define SURVCAP 4096           // survivor cap (slack threshold can exceed 2000)
#define PADF 512               // final-stage selection width (>= 100 + bin slack)
#define W_IMG 1333.0f
#define H_IMG 800.0f
#define SCORE_THR 0.05f
#define MAXPER 100
#define MAX_RATIO 4.135166556742356f   // |ln(16/1000)|
#define CLS_OFFSET 1334.0f             // max(H,W)+1

// ---------------- static scratch (no allocations allowed) ----------------
__device__ unsigned long long g_ckeys[BB][CC][CAPC];    // per-class buckets
__device__ int                g_ccnt[BB][CC];           // reset by k_final
__device__ unsigned long long g_T[BB];                  // top-2000-superset threshold
__device__ int                g_prefix[BB];             // lvl-0 straddle bin (-1 = take all)
__device__ int                g_above[BB];              // keys strictly above lvl-0 bin
__device__ unsigned long long g_skey[BB][SURVCAP];      // survivor keys
__device__ float4             g_sbox[BB][SURVCAP];      // survivor boxes
__device__ int                g_scnt[BB];               // reset by k_final
__device__ unsigned int       g_hist0[BB][2048];        // lvl-0 hist, bits 53+ (reset by k_score tail)
__device__ unsigned int       g_histL1[BB][2048];       // lvl-1 hist, bits 42-53 (reset by k_mid tail)
__device__ unsigned int       g_hist1[BB][2048];        // survivor lvl-0 hist (reset by k_final)
__device__ int                g_done0[BB];              // k_score completion (reset by tail)
__device__ int                g_done1[BB];              // k_mid completion (reset by tail)

// k_final fallback radix levels
__device__ __constant__ int c_shift[6] = {53, 42, 31, 20, 9, 0};
__device__ __constant__ int c_width[6] = {11, 11, 11, 11, 11, 9};

// ---- parallel straddle-bin search over s_hist[NB] (blockDim.x == 1024) ----
__device__ __forceinline__ void find_straddle(
    unsigned int* s_hist, int NB, int rank, int above0,
    int* s_bin, int* s_binh, int* s_bincg, unsigned int* s_wtot)
{
    int tid = threadIdx.x, lane = tid & 31, w = tid >> 5;
    int nw = NB >> 6;
    unsigned int h0 = 0, h1 = 0, tsum = 0;
    int b0 = tid * 2;
    if (b0 < NB) { h0 = s_hist[b0]; h1 = s_hist[b0 + 1]; tsum = h0 + h1; }
    unsigned int suf = tsum;
    #pragma unroll
    for (int off = 16; off; off >>= 1) {
        unsigned int t = __shfl_down_sync(0xffffffffu, suf, off);
        if (lane + off < 32) suf += t;
    }
    if (lane == 0 && w < nw) s_wtot[w] = suf;
    __syncthreads();
    if (w == 0) {
        unsigned int v = (lane < nw) ? s_wtot[lane] : 0u;
        unsigned int ws = v;
        #pragma unroll
        for (int off = 16; off; off >>= 1) {
            unsigned int t = __shfl_down_sync(0xffffffffu, ws, off);
            if (lane + off < 32) ws += t;
        }
        if (lane < nw) s_wtot[lane] = ws - v;
    }
    __syncthreads();
    if (b0 < NB) {
        unsigned int above_hi = s_wtot[w] + (suf - tsum);
        int a1 = above0 + (int)above_hi;
        int a0 = a1 + (int)h1;
        if (h1 && a1 < rank && a1 + (int)h1 >= rank) { *s_bin = b0 + 1; *s_binh = (int)h1; *s_bincg = a1; }
        if (h0 && a0 < rank && a0 + (int)h0 >= rank) { *s_bin = b0;     *s_binh = (int)h0; *s_bincg = a0; }
    }
    __syncthreads();
}

// ======= kernel 1: softmax + scatter (256 thr); tiny lvl-0 tail ==============
__global__ void __launch_bounds__(256)
k_score(const float* __restrict__ cls) {
    __shared__ unsigned int s_wtot[8];
    __shared__ int s_bin, s_a, s_tot, s_last;

    int tid = threadIdx.x;
    int row = (blockIdx.x * 256 + tid) >> 3;     // 32 rows per block
    int o = tid & 7;
    int lane = tid & 31;
    int w = tid >> 5;
    int b = row / NN;                            // block-uniform (32 | 4096)

    // ---- score phase ----
    {
        int n = row % NN;
        const float* p = cls + (size_t)row * CP1;
        float v[11];
        #pragma unroll
        for (int k = 0; k < 10; k++) v[k] = p[o + 8 * k];
        v[10] = (o == 0) ? p[80] : -1e30f;

        float m = v[0];
        #pragma unroll
        for (int k = 1; k < 11; k++) m = fmaxf(m, v[k]);
        #pragma unroll
        for (int off = 4; off; off >>= 1) m = fmaxf(m, __shfl_xor_sync(0xffffffffu, m, off));

        float e[11];
        float s = 0.f;
        #pragma unroll
        for (int k = 0; k < 11; k++) { e[k] = expf(v[k] - m); s += e[k]; }
        #pragma unroll
        for (int off = 4; off; off >>= 1) s += __shfl_xor_sync(0xffffffffu, s, off);

        #pragma unroll
        for (int k = 0; k < 10; k++) {
            float sc = e[k] / s;
            if (sc > SCORE_THR) {
                int c = o + 8 * k;
                unsigned int sb = __float_as_uint(sc);
                unsigned int lo = 0xFFFFFFFFu - (unsigned int)(n * CC + c);
                unsigned long long key = ((unsigned long long)sb << 32) | (unsigned long long)lo;
                int cp = atomicAdd(&g_ccnt[b][c], 1);
                if (cp < CAPC) g_ckeys[b][c][cp] = key;
                atomicAdd(&g_hist0[b][(unsigned int)(key >> 53)], 1u);
            }
        }
    }

    // ---- last of 128 blocks per image: lvl-0 straddle (no key scan) ----
    __threadfence();
    __syncthreads();
    if (tid == 0) {
        int old = atomicAdd(&g_done0[b], 1);
        s_last = (old == 127) ? 1 : 0;
    }
    __syncthreads();
    if (!s_last) return;

    unsigned int hv[8];
    int base = tid * 8;
    unsigned int sum = 0;
    #pragma unroll
    for (int j = 0; j < 8; j++) {
        hv[j] = g_hist0[b][base + j];
        g_hist0[b][base + j] = 0u;               // reset for next replay
        sum += hv[j];
    }
    if (tid == 0) { g_done0[b] = 0; s_bin = 0; }
    unsigned int suf = sum;                      // warp inclusive suffix
    #pragma unroll
    for (int off = 16; off; off >>= 1) {
        unsigned int t = __shfl_down_sync(0xffffffffu, suf, off);
        if (lane + off < 32) suf += t;
    }
    if (lane == 0) s_wtot[w] = suf;
    __syncthreads();
    if (w == 0) {                                // exclusive suffix over 8 warps
        unsigned int v = (lane < 8) ? s_wtot[lane] : 0u;
        unsigned int ws = v;
        #pragma unroll
        for (int off = 16; off; off >>= 1) {
            unsigned int t = __shfl_down_sync(0xffffffffu, ws, off);
            if (lane + off < 32) ws += t;
        }
        if (lane < 8) s_wtot[lane] = ws - v;
        if (lane == 0) s_tot = (int)ws;          // total candidates
    }
    __syncthreads();
    {
        unsigned int cg = s_wtot[w] + (suf - sum);   // keys strictly above my chunk
        #pragma unroll
        for (int j = 7; j >= 0; j--) {
            unsigned int h = hv[j];
            int a = (int)cg;
            if (h && a < KPRE && a + (int)h >= KPRE) { s_bin = base + j; s_a = a; }
            cg += h;
        }
    }
    __syncthreads();
    if (tid == 0) {
        if (s_tot <= KPRE) { g_prefix[b] = -1; g_T[b] = 1ULL; }
        else { g_prefix[b] = s_bin; g_above[b] = s_a; }
    }
}

// ======= kernel 2: parallel lvl-1 histogram (one block per class, image) =====
__global__ void __launch_bounds__(128)
k_mid() {
    __shared__ unsigned int s_wtot[4];
    __shared__ int s_bin, s_last;

    int c = blockIdx.x;
    int b = blockIdx.y;
    int tid = threadIdx.x;
    int lane = tid & 31;
    int w = tid >> 5;

    int pfx = g_prefix[b];
    if (pfx >= 0) {
        int cnt = g_ccnt[b][c]; if (cnt > CAPC) cnt = CAPC;
        for (int i = tid; i < cnt; i += 128) {
            unsigned long long k = g_ckeys[b][c][i];
            if ((unsigned int)(k >> 53) == (unsigned int)pfx)
                atomicAdd(&g_histL1[b][(unsigned int)(k >> 42) & 2047u], 1u);
        }
    }

    __threadfence();
    __syncthreads();
    if (tid == 0) {
        int old = atomicAdd(&g_done1[b], 1);
        s_last = (old == CC - 1) ? 1 : 0;
    }
    __syncthreads();
    if (!s_last) return;

    // tail: straddle lvl-1 hist (16 bins/thread), unconditional slack accept
    if (tid == 0) { g_done1[b] = 0; s_bin = 0; }
    int above0 = (pfx >= 0) ? g_above[b] : 0;
    unsigned int hv[16];
    int base = tid * 16;
    unsigned int sum = 0;
    #pragma unroll
    for (int j = 0; j < 16; j++) {
        hv[j] = g_histL1[b][base + j];
        g_histL1[b][base + j] = 0u;              // reset for next replay
        sum += hv[j];
    }
    unsigned int suf = sum;
    #pragma unroll
    for (int off = 16; off; off >>= 1) {
        unsigned int t = __shfl_down_sync(0xffffffffu, suf, off);
        if (lane + off < 32) suf += t;
    }
    if (lane == 0) s_wtot[w] = suf;
    __syncthreads();
    if (w == 0) {                                // exclusive suffix over 4 warps
        unsigned int v = (lane < 4) ? s_wtot[lane] : 0u;
        unsigned int ws = v;
        #pragma unroll
        for (int off = 16; off; off >>= 1) {
            unsigned int t = __shfl_down_sync(0xffffffffu, ws, off);
            if (lane + off < 32) ws += t;
        }
        if (lane < 4) s_wtot[lane] = ws - v;
    }
    __syncthreads();
    {
        unsigned int cg = (unsigned int)above0 + s_wtot[w] + (suf - sum);
        #pragma unroll
        for (int j = 15; j >= 0; j--) {
            unsigned int h = hv[j];
            int a = (int)cg;
            if (h && a < KPRE && a + (int)h >= KPRE) s_bin = base + j;
            cg += h;
        }
    }
    __syncthreads();
    if (tid == 0 && pfx >= 0) {
        // slack accept: T = lvl-1 bin floor. Extras below true rank-2000 are
        // provably inert (sort last per class; >>100 member survivors exist).
        g_T[b] = ((unsigned long long)(unsigned int)pfx << 53)
               | ((unsigned long long)(unsigned int)s_bin << 42);
    }
}

// ---------------- 3: per-class NMS, one 128-thread block per (class, image) --
__global__ void k_nms(const float* __restrict__ reg, const float* __restrict__ rois) {
    __shared__ unsigned long long s_k[NMSCAP];
    __shared__ float4             s_bx[NMSCAP];
    __shared__ unsigned char      s_sup[NMSCAP];
    __shared__ short              s_keep[NMSCAP];
    __shared__ int s_cnt, s_n, s_nk, s_base;

    int c = blockIdx.x;
    int b = blockIdx.y;
    int tid = threadIdx.x;
    int lane = tid & 31;

    if (tid == 0) {
        int cc = g_ccnt[b][c]; if (cc > CAPC) cc = CAPC;
        s_cnt = cc;
        s_n = 0; s_nk = 0; s_base = 0;
    }
    __syncthreads();
    int cnt = s_cnt;
    unsigned long long T = g_T[b];

    // filter >= T, warp-aggregated append (uniform trips)
    int iters = (cnt + 127) >> 7;
    for (int it = 0; it < iters; it++) {
        int i = (it << 7) + tid;
        unsigned long long k = (i < cnt) ? g_ckeys[b][c][i] : 0ULL;
        bool f = (i < cnt) && (k >= T);
        unsigned bal = __ballot_sync(0xffffffffu, f);
        int wc = __popc(bal);
        int base = 0;
        if (lane == 0 && wc) base = atomicAdd(&s_n, wc);
        base = __shfl_sync(0xffffffffu, base, 0);
        if (f) {
            int pos = base + __popc(bal & ((1u << lane) - 1));
            if (pos < NMSCAP) s_k[pos] = k;
        }
    }
    __syncthreads();
    int n = s_n; if (n > NMSCAP) n = NMSCAP;

    // pad to pow2; warp-0 bitonic sort (descending), __syncwarp only
    int p = 2; while (p < n) p <<= 1;
    for (int i = n + tid; i < p; i += blockDim.x) s_k[i] = 0ULL;
    __syncthreads();
    if (tid < 32) {
        for (int k2 = 2; k2 <= p; k2 <<= 1) {
            for (int j = k2 >> 1; j > 0; j >>= 1) {
                for (int i = lane; i < p; i += 32) {
                    int ixj = i ^ j;
                    if (ixj > i) {
                        unsigned long long a = s_k[i];
                        unsigned long long d = s_k[ixj];
                        bool desc = ((i & k2) == 0);
                        if (desc ? (a < d) : (a > d)) { s_k[i] = d; s_k[ixj] = a; }
                    }
                }
                __syncwarp();
            }
        }
    }
    __syncthreads();

    // decode + clip
    for (int i = tid; i < n; i += blockDim.x) {
        unsigned long long key = s_k[i];
        unsigned int idx = 0xFFFFFFFFu - (unsigned int)(key & 0xFFFFFFFFu);
        int nn = idx / CC;
        const float* r = rois + ((size_t)b * NN + nn) * 4;
        float x1 = r[0], y1 = r[1], x2 = r[2], y2 = r[3];
        float px = (x1 + x2) * 0.5f;
        float py = (y1 + y2) * 0.5f;
        float pw = x2 - x1;
        float ph = y2 - y1;
        const float* d = reg + ((size_t)b * NN + nn) * (4 * CC) + 4 * c;
        float dx = d[0] * 0.1f;
        float dy = d[1] * 0.1f;
        float dw = fminf(d[2] * 0.2f, MAX_RATIO);
        float dh = fminf(d[3] * 0.2f, MAX_RATIO);
        float gx = px + pw * dx;
        float gy = py + ph * dy;
        float gw = pw * expf(dw);
        float gh = ph * expf(dh);
        float bx1 = gx - gw * 0.5f, by1 = gy - gh * 0.5f;
        float bx2 = gx + gw * 0.5f, by2 = gy + gh * 0.5f;
        bx1 = fminf(fmaxf(bx1, 0.f), W_IMG);
        bx2 = fminf(fmaxf(bx2, 0.f), W_IMG);
        by1 = fminf(fmaxf(by1, 0.f), H_IMG);
        by2 = fminf(fmaxf(by2, 0.f), H_IMG);
        s_bx[i] = make_float4(bx1, by1, bx2, by2);
        s_sup[i] = 0;
    }
    __syncthreads();

    // greedy NMS (warp 0); IoU on OFFSET boxes = exact reference arithmetic
    if (tid < 32) {
        float off = (float)c * CLS_OFFSET;
        for (int ii = 0; ii < n; ii++) {
            if (!s_sup[ii]) {
                float4 bi = s_bx[ii];
                bi.x += off; bi.y += off; bi.z += off; bi.w += off;
                float ai = (bi.z - bi.x) * (bi.w - bi.y);
                for (int jj = ii + 1 + lane; jj < n; jj += 32) {
                    float4 bj = s_bx[jj];
                    bj.x += off; bj.y += off; bj.z += off; bj.w += off;
                    float xx1 = fmaxf(bi.x, bj.x);
                    float yy1 = fmaxf(bi.y, bj.y);
                    float xx2 = fminf(bi.z, bj.z);
                    float yy2 = fminf(bi.w, bj.w);
                    float iw = fmaxf(xx2 - xx1, 0.f);
                    float ih = fmaxf(yy2 - yy1, 0.f);
                    float inter = iw * ih;
                    float aj = (bj.z - bj.x) * (bj.w - bj.y);
                    float uni = fmaxf(ai + aj - inter, 1e-6f);
                    if (inter / uni > 0.5f) s_sup[jj] = 1;
                }
            }
            __syncwarp();
        }
        if (lane == 0) {
            int mkeep = 0;
            for (int i = 0; i < n; i++)
                if (!s_sup[i]) s_keep[mkeep++] = (short)i;
            s_nk = mkeep;
            if (mkeep) s_base = atomicAdd(&g_scnt[b], mkeep);
        }
    }
    __syncthreads();
    int nk = s_nk, sb = s_base;
    for (int i = tid; i < nk; i += blockDim.x) {
        if (sb + i < SURVCAP) {
            int src = s_keep[i];
            unsigned long long k = s_k[src];
            g_skey[b][sb + i] = k;
            g_sbox[b][sb + i] = s_bx[src];
            atomicAdd(&g_hist1[b][(unsigned int)(k >> 53) & 2047u], 1u);
        }
    }
}

// ---------------- 4: top-100 of survivors by RANK, output, resets ------------
__global__ void __launch_bounds__(1024)
k_final(float* __restrict__ out) {
    __shared__ unsigned int       s_hist[2048];
    __shared__ unsigned int       s_wtot[32];
    __shared__ unsigned long long s_prefix;
    __shared__ unsigned long long s_T;
    __shared__ int s_above, s_done, s_S, s_cnt;
    __shared__ int s_bin, s_binh, s_bincg;
    __shared__ unsigned long long s_k2[PADF];
    __shared__ short              s_slot[PADF];

    int b = blockIdx.x;
    int tid = threadIdx.x;
    int lane = tid & 31;
    const unsigned long long* keys = g_skey[b];

    if (tid == 0) {
        int S = g_scnt[b]; if (S > SURVCAP) S = SURVCAP;
        s_S = S;
        s_prefix = 0ULL;
        s_above = 0;
        s_done = (S <= PADF) ? 1 : 0;
        s_T = 1ULL;
        s_cnt = 0;
    }
    __syncthreads();
    int S = s_S;

    // rank-100 radix with slack; level 0 hist precomputed by k_nms
    for (int level = 0; level < 6 && !s_done; level++) {
        int shift = c_shift[level];
        int width = c_width[level];
        int NB = 1 << width;
        if (level == 0) {
            for (int i = tid; i < 2048; i += 1024) s_hist[i] = g_hist1[b][i];
        } else {
            unsigned long long pmask = (~0ULL) << (shift + width);
            for (int i = tid; i < 2048; i += 1024) s_hist[i] = 0;
            __syncthreads();
            unsigned long long pref = s_prefix;
            for (int i = tid; i < S; i += 1024) {
                unsigned long long k = keys[i];
                if ((k & pmask) == pref)
                    atomicAdd(&s_hist[(unsigned int)(k >> shift) & (NB - 1)], 1u);
            }
        }
        if (tid == 0) s_binh = 0;
        __syncthreads();
        find_straddle(s_hist, NB, MAXPER, s_above, &s_bin, &s_binh, &s_bincg, s_wtot);
        if (tid == 0) {
            int a = s_bincg, h = s_binh;
            unsigned long long binv = (unsigned long long)s_bin << shift;
            if (h == 0) { s_done = 1; }
            else if (a + h <= PADF) { s_T = s_prefix | binv; s_done = 1; }
            else { s_prefix = s_prefix | binv; s_above = a; }
        }
        __syncthreads();
    }
    unsigned long long T2 = s_T;

    // compact (key, slot) pairs >= T2 directly from global (uniform trips)
    {
        int iters = (S + 1023) >> 10;
        for (int it = 0; it < iters; it++) {
            int i = (it << 10) + tid;
            unsigned long long k = (i < S) ? keys[i] : 0ULL;
            bool f = (i < S) && (k >= T2);
            unsigned bal = __ballot_sync(0xffffffffu, f);
            int wc = __popc(bal);
            int base = 0;
            if (lane == 0 && wc) base = atomicAdd(&s_cnt, wc);
            base = __shfl_sync(0xffffffffu, base, 0);
            if (f) {
                int pos = base + __popc(bal & ((1u << lane) - 1));
                if (pos < PADF) { s_k2[pos] = k; s_slot[pos] = (short)i; }
            }
        }
    }
    __syncthreads();
    int cf = s_cnt; if (cf > PADF) cf = PADF;

    // prefill output with empty slots
    if (tid < MAXPER) {
        float* po = out + ((size_t)b * MAXPER + tid) * 4;
        po[0] = 0.f; po[1] = 0.f; po[2] = 0.f; po[3] = 0.f;
        out[BB * MAXPER * 4 + b * MAXPER + tid] = 0.f;
        out[BB * MAXPER * 4 + BB * MAXPER + b * MAXPER + tid] = -1.f;
    }
    __syncthreads();

    // rank selection: keys unique -> exact permutation; rank < 100 writes slot
    if (tid < cf) {
        unsigned long long mykey = s_k2[tid];
        int r = 0;
        for (int j = 0; j < cf; j++) r += (s_k2[j] > mykey) ? 1 : 0;
        if (r < MAXPER) {
            float4 bb = g_sbox[b][s_slot[tid]];
            float sc = __uint_as_float((unsigned int)(mykey >> 32));
            unsigned int idx = 0xFFFFFFFFu - (unsigned int)(mykey & 0xFFFFFFFFu);
            float lb = (float)(idx % CC);
            float* po = out + ((size_t)b * MAXPER + r) * 4;
            po[0] = bb.x; po[1] = bb.y; po[2] = bb.z; po[3] = bb.w;
            out[BB * MAXPER * 4 + b * MAXPER + r] = sc;
            out[BB * MAXPER * 4 + BB * MAXPER + b * MAXPER + r] = lb;
        }
    }

    // global resets for next graph replay
    for (int i = tid; i < 2048; i += 1024) g_hist1[b][i] = 0u;
    if (tid < CC) g_ccnt[b][tid] = 0;
    if (tid == 0) g_scnt[b] = 0;
}

extern "C" void kernel_launch(void* const* d_in, const int* in_sizes, int n_in,
                              void* d_out, int out_size) {
    const float* cls  = (const float*)d_in[0];   // [B,N,81]
    const float* reg  = (const float*)d_in[1];   // [B,N,320]
    const float* rois = (const float*)d_in[2];   // [B,N,4]
    float* out = (float*)d_out;

    k_score<<<BB * NN * 8 / 256, 256>>>(cls);
    k_mid<<<dim3(CC, BB), 128>>>();
    k_nms<<<dim3(CC, BB), 128>>>(reg, rois);
    k_final<<<BB, 1024>>>(out);
}